// round 6
// baseline (speedup 1.0000x reference)
#include <cuda_runtime.h>

// Reference collapses: softmax(const(-9e15)) == uniform 1/N  =>  adj/a/e dead.
//   out[i,:] = relu( (colsum(h) @ W) / N )  -- one 64-float row broadcast 8192x.
// One kernel, grid = 148 (one block/SM):
//   A: grid-stride partial column sums (16MB coalesced)
//   B: per-block projection through W -> 64 floats -> g_pproj[b]
//   C: per-slot done flags (plain stores, monotonic; NO atomics), warp-0 poll
//   D: every block redundantly sums 148x64 partials (fixed order), relu, writes slice.

#define N_ROWSC 8192
#define F_INC   512
#define F_OUTC  64
#define GRID    148
#define THREADS 1024
#define TOTAL_F4 (N_ROWSC * F_INC / 4)        // 1,048,576
#define STRIDE   (GRID * THREADS)             // 151,552 (multiple of 128)
#define FULL_IT  6                            // 6*151552 = 909,312
#define REM      (TOTAL_F4 - FULL_IT * STRIDE) // 139,264
#define OUT_F4   (N_ROWSC * F_OUTC / 4)       // 131,072

__device__ float g_pproj[GRID * F_OUTC];      // per-block projected partials (37 KB)
__device__ volatile unsigned g_done[GRID];    // per-block completion epochs (monotonic)

__global__ __launch_bounds__(THREADS)
void gat_kernel(const float4* __restrict__ h4,
                const float*  __restrict__ W,
                const float4* __restrict__ W4,
                float4*       __restrict__ out)
{
    __shared__ float4 s4[THREADS];            // 16 KB
    __shared__ float4 sf4[F_INC / 4];         // 2 KB block colsum
    __shared__ float  pp[16 * F_OUTC];        // 4 KB
    __shared__ float4 srow4[F_OUTC / 4];      // 256 B
    __shared__ unsigned s_target;

    const int t = threadIdx.x;
    const int b = blockIdx.x;
    const float* sf = (const float*)sf4;

    // Warm W (131 KB) into L2 early; sink keeps the loads alive.
    if (b < 32 && t < 256) {
        float4 w = __ldcg(&W4[b * 256 + t]);
        asm volatile("" :: "f"(w.x), "f"(w.y), "f"(w.z), "f"(w.w));
    }

    // ---- A: partial column sums, grid-stride, fully coalesced ----
    {
        const int gid = b * THREADS + t;      // stride mult of 128 -> colgrp = t & 127
        float4 acc = make_float4(0.f, 0.f, 0.f, 0.f);
        #pragma unroll
        for (int k = 0; k < FULL_IT; ++k) {
            float4 v = h4[gid + k * STRIDE];
            acc.x += v.x; acc.y += v.y; acc.z += v.z; acc.w += v.w;
        }
        if (gid < REM) {
            float4 v = h4[gid + FULL_IT * STRIDE];
            acc.x += v.x; acc.y += v.y; acc.z += v.z; acc.w += v.w;
        }
        s4[t] = acc;
    }
    __syncthreads();
    if (t < 128) {                            // fixed order -> deterministic
        float4 a = s4[t];
        #pragma unroll
        for (int j = 1; j < 8; ++j) {
            float4 v = s4[t + 128 * j];       // same column group t
            a.x += v.x; a.y += v.y; a.z += v.z; a.w += v.w;
        }
        sf4[t] = a;
    }
    __syncthreads();

    // ---- B: project local colsum through W (col = t&63, 16 k-slices of 32) ----
    {
        const int col = t & 63;
        const int sl  = t >> 6;
        float o = 0.f;
        #pragma unroll 8
        for (int i = 0; i < 32; ++i) {
            const int k = sl * 32 + i;
            o = fmaf(sf[k], W[k * F_OUTC + col], o);   // W is L2-warm, coalesced
        }
        pp[sl * F_OUTC + col] = o;
    }
    __syncthreads();
    if (t < F_OUTC) {                         // fixed combine order
        float v = 0.f;
        #pragma unroll
        for (int sl = 0; sl < 16; ++sl) v += pp[sl * F_OUTC + t];
        g_pproj[b * F_OUTC + t] = v;          // un-normalized local projection
    }
    __threadfence();
    __syncthreads();

    // ---- C: per-slot done flag (plain store; own slot only -> race-free) ----
    if (t == 0) {
        unsigned cur = g_done[b];             // epochs completed so far (this block)
        s_target = cur + 1;
        g_done[b] = cur + 1;                  // release (fence above)
    }
    __syncthreads();
    const unsigned target = s_target;

    // Warp 0 polls all 148 slots (plain reads, no RMW contention).
    if (t < 32) {
        bool ok;
        do {
            ok = true;
            #pragma unroll
            for (int s = t; s < GRID; s += 32) ok &= (g_done[s] >= target);
            ok = __all_sync(0xffffffffu, ok);
            if (!ok) __nanosleep(128);
        } while (!ok);
    }
    __syncthreads();
    __threadfence();                          // acquire before reading g_pproj

    // ---- D: every block sums 148 projection partials (fixed order), relu ----
    {
        const int col = t & 63;
        const int sl  = t >> 6;               // 16 slices over 148 blocks: 4x10 + 12x9
        const int start = sl * 9 + (sl < 4 ? sl : 4);
        const int cnt   = 9 + (sl < 4 ? 1 : 0);
        float v = 0.f;
        for (int j = 0; j < cnt; ++j)
            v += __ldcg(&g_pproj[(start + j) * F_OUTC + col]);
        pp[sl * F_OUTC + col] = v;
    }
    __syncthreads();
    if (t < F_OUTC) {                         // fixed combine order
        float v = 0.f;
        #pragma unroll
        for (int sl = 0; sl < 16; ++sl) v += pp[sl * F_OUTC + t];
        v *= (1.0f / (float)N_ROWSC);
        ((float*)srow4)[t] = fmaxf(v, 0.0f);
    }
    __syncthreads();

    // ---- Output: blocks 0..127 each write their exact 4 KB slice ----
    const int idx = b * THREADS + t;
    if (idx < OUT_F4)
        out[idx] = srow4[t & 15];             // 1024 mult of 16 -> colgrp = t & 15
}

extern "C" void kernel_launch(void* const* d_in, const int* in_sizes, int n_in,
                              void* d_out, int out_size) {
    (void)in_sizes; (void)n_in; (void)out_size;
    const float* h = (const float*)d_in[0];   // (8192, 512) fp32
    // d_in[1] = adj (8192,8192) -- dead code, never read
    const float* W = (const float*)d_in[2];   // (512, 64) fp32
    // d_in[3] = a (128,1)       -- dead code, never read
    float* out = (float*)d_out;               // (8192, 64) fp32

    gat_kernel<<<GRID, THREADS>>>((const float4*)h, W, (const float4*)W,
                                  (float4*)out);
}

// round 8
// speedup vs baseline: 1.2103x; 1.2103x over previous
#include <cuda_runtime.h>

// Reference collapses: softmax(const(-9e15)) == uniform 1/N  =>  adj/a/e dead.
//   out[i,:] = relu( (colsum(h) @ W) / N )  -- one 64-float row broadcast 8192x.
// One kernel, grid 128 x 512:
//   A: partial column sums, 2x8 front-batched float4 loads/thread (MLP ~8-16)
//   B: per-block projection through W -> g_pproj[b] (64 floats)
//   C: ticket; last-arriving block reduces 128x64 partials, relu -> g_row, flag
//   D: all blocks spin on one flag, broadcast 2MB output.

#define N_ROWSC 8192
#define F_INC   512
#define F_OUTC  64
#define GRID    128
#define THREADS 512
#define TOTAL_F4 (N_ROWSC * F_INC / 4)        // 1,048,576
#define STRIDE   (GRID * THREADS)             // 65,536 (multiple of 128)
#define LOADS_PT (TOTAL_F4 / STRIDE)          // 16 (exact)
#define WAVE     8                            // loads per batch
#define OUT_F4   (N_ROWSC * F_OUTC / 4)       // 131,072

__device__ float g_pproj[GRID * F_OUTC];          // 32 KB per-block projections
__device__ float g_row[F_OUTC];
__device__ unsigned long long g_cnt;              // monotonic across replays
__device__ volatile unsigned long long g_flag;    // epoch of completed row

__global__ __launch_bounds__(THREADS)
void gat_kernel(const float4* __restrict__ h4,
                const float*  __restrict__ W,
                const float4* __restrict__ W4,
                float4*       __restrict__ out)
{
    __shared__ float4 s4[THREADS];            // 8 KB
    __shared__ float  sf[F_INC];              // 2 KB block colsum
    __shared__ float  pp[8 * F_OUTC];         // 2 KB
    __shared__ float4 srow4[F_OUTC / 4];      // 256 B
    __shared__ unsigned long long s_ticket;

    const int t = threadIdx.x;
    const int b = blockIdx.x;

    // Warm W (131 KB = 8192 float4) into L2; blocks 0..15 cover it exactly.
    if (b < 16) {
        float4 w = __ldcg(&W4[b * THREADS + t]);
        asm volatile("" :: "f"(w.x), "f"(w.y), "f"(w.z), "f"(w.w));
    }

    // ---- A: partial column sums; two waves of 8 front-batched float4 loads ----
    {
        const int gid = b * THREADS + t;      // stride mult of 128 -> colgrp = t & 127
        float4 acc = make_float4(0.f, 0.f, 0.f, 0.f);
        #pragma unroll
        for (int w = 0; w < LOADS_PT / WAVE; ++w) {
            float4 v[WAVE];
            #pragma unroll
            for (int k = 0; k < WAVE; ++k)    // 8 independent loads in flight
                v[k] = h4[gid + (w * WAVE + k) * STRIDE];
            #pragma unroll
            for (int k = 0; k < WAVE; ++k) {  // fixed order -> deterministic
                acc.x += v[k].x; acc.y += v[k].y;
                acc.z += v[k].z; acc.w += v[k].w;
            }
        }
        s4[t] = acc;
    }
    __syncthreads();
    if (t < 128) {                            // 4 partials per column group, fixed order
        float4 a = s4[t];
        #pragma unroll
        for (int j = 1; j < 4; ++j) {
            float4 v = s4[t + 128 * j];
            a.x += v.x; a.y += v.y; a.z += v.z; a.w += v.w;
        }
        sf[t * 4 + 0] = a.x; sf[t * 4 + 1] = a.y;
        sf[t * 4 + 2] = a.z; sf[t * 4 + 3] = a.w;
    }
    __syncthreads();

    // ---- B: project local colsum through W (col = t&63, 8 k-slices of 64) ----
    {
        const int col = t & 63;
        const int sl  = t >> 6;               // 0..7
        float o = 0.f;
        #pragma unroll 8
        for (int i = 0; i < 64; ++i) {
            const int k = sl * 64 + i;
            o = fmaf(sf[k], W[k * F_OUTC + col], o);   // W is L2-warm, coalesced
        }
        pp[sl * F_OUTC + col] = o;
    }
    __syncthreads();
    if (t < F_OUTC) {                         // fixed combine order
        float v = 0.f;
        #pragma unroll
        for (int sl = 0; sl < 8; ++sl) v += pp[sl * F_OUTC + t];
        g_pproj[b * F_OUTC + t] = v;
    }
    __threadfence();
    __syncthreads();

    if (t == 0) s_ticket = atomicAdd(&g_cnt, 1ULL);
    __syncthreads();
    const unsigned long long ticket = s_ticket;
    const unsigned long long launch = ticket / GRID;   // replay epoch

    if (ticket % GRID == GRID - 1) {
        // ---- C: last arrival reduces 128x64 projections (32 KB, L2) ----
        {
            const int col = t & 63;
            const int sl  = t >> 6;           // 8 slices x 16 blocks
            float v = 0.f;
            #pragma unroll
            for (int j = 0; j < GRID / 8; ++j)
                v += __ldcg(&g_pproj[(sl * (GRID / 8) + j) * F_OUTC + col]);
            pp[sl * F_OUTC + col] = v;
        }
        __syncthreads();
        if (t < F_OUTC) {                     // fixed combine order
            float v = 0.f;
            #pragma unroll
            for (int sl = 0; sl < 8; ++sl) v += pp[sl * F_OUTC + t];
            v *= (1.0f / (float)N_ROWSC);
            g_row[t] = fmaxf(v, 0.0f);
        }
        __threadfence();
        __syncthreads();
        if (t == 0) g_flag = launch + 1;      // release (fence above)
    } else {
        // ---- Waiters: single plain-load spin on one word (no RMW) ----
        if (t == 0) {
            while (g_flag < launch + 1) __nanosleep(64);
            __threadfence();                  // acquire
        }
        __syncthreads();
    }

    // ---- D: broadcast; each block writes 1024 float4 (2 per thread) ----
    if (t < F_OUTC / 4) srow4[t] = __ldcg(((const float4*)g_row) + t);
    __syncthreads();
    const int i0 = b * (OUT_F4 / GRID) + t;   // OUT_F4/GRID = 1024
    out[i0]           = srow4[t & 15];        // 512 mult of 16 -> same colgrp
    out[i0 + THREADS] = srow4[t & 15];
}

extern "C" void kernel_launch(void* const* d_in, const int* in_sizes, int n_in,
                              void* d_out, int out_size) {
    (void)in_sizes; (void)n_in; (void)out_size;
    const float* h = (const float*)d_in[0];   // (8192, 512) fp32
    // d_in[1] = adj (8192,8192) -- dead code, never read
    const float* W = (const float*)d_in[2];   // (512, 64) fp32
    // d_in[3] = a (128,1)       -- dead code, never read
    float* out = (float*)d_out;               // (8192, 64) fp32

    gat_kernel<<<GRID, THREADS>>>((const float4*)h, W, (const float4*)W,
                                  (float4*)out);
}